// round 2
// baseline (speedup 1.0000x reference)
#include <cuda_runtime.h>
#include <cuda_bf16.h>
#include <cstdint>

// ClusteredLinear: out[b,c,p] = sum_s x[b,c,s] * W[clusters[c],p,s] + bias[clusters[c],p]
// Shapes: x [64, 862, 720] f32, clusters [862] int32 (JAX downcasts int64->int32
// without x64 mode), W [8, 336, 720] f32, b [8, 336] f32, out [64, 862, 336] f32.
//
// Baseline: per-channel 64x336x720 FP32 GEMM. Block = (channel c, 64-wide N tile).
// TM=64 (all batches), TN=64, BK=16, 256 threads, 4x4 microtile.
// SMEM staged k-major ([BK][TM+pad]) so the inner loop uses 128-bit LDS with no
// conflicts; global loads are float4 along S (S=720 -> 16B aligned everywhere).

#define B_DIM 64
#define C_DIM 862
#define S_DIM 720
#define P_DIM 336
#define NCLUST 8

#define TM 64
#define TN 64
#define BK 16
#define PAD 68   // row stride in floats for [BK][*] smem tiles (272B = 17*16, float4-aligned)

__global__ __launch_bounds__(256, 4)
void clustered_linear_kernel(const float* __restrict__ x,
                             const int* __restrict__ clusters,
                             const float* __restrict__ W,
                             const float* __restrict__ bias,
                             float* __restrict__ out)
{
    const int c  = blockIdx.y;             // channel
    const int n0 = blockIdx.x * TN;        // N-tile base (0,64,...,320)
    int kcl = clusters[c];
    // Defensive clamp: if the dtype assumption is ever wrong, fail with finite
    // rel_err instead of an illegal memory access.
    kcl = min(max(kcl, 0), NCLUST - 1);

    const float* Wbase = W + (size_t)kcl * P_DIM * S_DIM;

    __shared__ float xs[BK][PAD];   // xs[k][m]
    __shared__ float ws[BK][PAD];   // ws[k][n]

    const int t  = threadIdx.x;
    const int tx = t & 15;          // -> N microtile
    const int ty = t >> 4;          // -> M microtile

    // Loader mapping: each thread owns one float4 of one row per BK-chunk.
    const int lrow = t >> 2;        // 0..63 (m for x, local n for W)
    const int lq   = t & 3;         // which float4 along K

    const float* xrow = x + ((size_t)lrow * C_DIM + c) * S_DIM;   // batch=lrow
    const int    ng   = n0 + lrow;                                 // global output col
    const bool   wok  = (ng < P_DIM);
    const float* wrow = Wbase + (size_t)(wok ? ng : 0) * S_DIM;

    float acc[4][4] = {};

    for (int k0 = 0; k0 < S_DIM; k0 += BK) {
        float4 xv = *(const float4*)(xrow + k0 + lq * 4);
        float4 wv = wok ? *(const float4*)(wrow + k0 + lq * 4)
                        : make_float4(0.f, 0.f, 0.f, 0.f);
        __syncthreads();   // previous iteration's smem reads done
        xs[lq * 4 + 0][lrow] = xv.x;
        xs[lq * 4 + 1][lrow] = xv.y;
        xs[lq * 4 + 2][lrow] = xv.z;
        xs[lq * 4 + 3][lrow] = xv.w;
        ws[lq * 4 + 0][lrow] = wv.x;
        ws[lq * 4 + 1][lrow] = wv.y;
        ws[lq * 4 + 2][lrow] = wv.z;
        ws[lq * 4 + 3][lrow] = wv.w;
        __syncthreads();

        #pragma unroll
        for (int k = 0; k < BK; ++k) {
            float4 a  = *(const float4*)&xs[k][ty * 4];
            float4 bv = *(const float4*)&ws[k][tx * 4];
            float av[4] = {a.x, a.y, a.z, a.w};
            float bb[4] = {bv.x, bv.y, bv.z, bv.w};
            #pragma unroll
            for (int i = 0; i < 4; ++i)
                #pragma unroll
                for (int j = 0; j < 4; ++j)
                    acc[i][j] = fmaf(av[i], bb[j], acc[i][j]);
        }
    }

    // Epilogue: add bias, store float4 rows (P=336 divisible by 4; each thread's
    // 4 columns are either fully in-range or fully out since ncol is 4-aligned).
    const int ncol = n0 + tx * 4;
    if (ncol < P_DIM) {
        const float* brow = bias + (size_t)kcl * P_DIM + ncol;
        float4 bb = *(const float4*)brow;
        #pragma unroll
        for (int i = 0; i < 4; ++i) {
            const int m = ty * 4 + i;
            float4 r;
            r.x = acc[i][0] + bb.x;
            r.y = acc[i][1] + bb.y;
            r.z = acc[i][2] + bb.z;
            r.w = acc[i][3] + bb.w;
            *(float4*)(out + ((size_t)m * C_DIM + c) * P_DIM + ncol) = r;
        }
    }
}

extern "C" void kernel_launch(void* const* d_in, const int* in_sizes, int n_in,
                              void* d_out, int out_size)
{
    const float* x        = (const float*)d_in[0];
    const int*   clusters = (const int*)d_in[1];
    const float* W        = (const float*)d_in[2];
    const float* bias     = (const float*)d_in[3];
    float*       out      = (float*)d_out;

    dim3 grid((P_DIM + TN - 1) / TN, C_DIM);   // 6 x 862
    clustered_linear_kernel<<<grid, 256>>>(x, clusters, W, bias, out);
}

// round 4
// speedup vs baseline: 2.2671x; 2.2671x over previous
#include <cuda_runtime.h>
#include <cuda_bf16.h>
#include <cstdint>

// ClusteredLinear via cluster-paired bf16-split mma.sync GEMM (family-portable:
// no tcgen05 -- harness compiles at compute_103, not compute_103a).
// out[b,c,p] = sum_s x[b,c,s]*W[cl[c],p,s] + bias[cl[c],p]
// x [64,862,720] f32, clusters [862] i32, W [8,336,720] f32, bias [8,336] f32,
// out [64,862,336] f32.
//
// 1) convert_x/convert_w: f32 -> bf16 hi/lo split scratch.
//    3 passes xh*wh + xh*wl + xl*wh, fp32 accum -> ~1e-5 rel err.
// 2) build_order: cluster-sorted channel list, per-cluster padded even (-1).
// 3) gemm: CTA tile M=128 (2 same-cluster channels x 64 batch) x N=112,
//    8 warps (4M x 2N), warp tile m32n56 of m16n8k16 HMMA.
//    K chunks of 32, 4-stage cp.async pipeline, 80B-padded smem rows
//    (conflict-free ldmatrix without xor swizzle).

#define B_DIM 64
#define C_DIM 862
#define S_DIM 720
#define P_DIM 336
#define NCLUST 8

#define TILE_N 112
#define KC 32
#define NCHUNKS 23          // 22 full + 16-elem tail (zero padded)
#define NSTAGES 4
#define NTILES 435
#define NPAD 880

#define ROWB 80                       // padded smem row stride (bytes)
#define OFF_AH 0
#define OFF_AL (128*ROWB)             // 10240
#define OFF_BH (OFF_AL + 128*ROWB)    // 20480
#define OFF_BL (OFF_BH + TILE_N*ROWB) // 29440
#define STAGE_B (OFF_BL + TILE_N*ROWB)// 38400
#define SMEM_TOTAL (NSTAGES*STAGE_B)  // 153600

// ---- scratch (__device__ globals: allocation-free rule) ----
__device__ __nv_bfloat16 g_xh[(size_t)B_DIM*C_DIM*S_DIM];
__device__ __nv_bfloat16 g_xl[(size_t)B_DIM*C_DIM*S_DIM];
__device__ __nv_bfloat16 g_wh[(size_t)NCLUST*P_DIM*S_DIM];
__device__ __nv_bfloat16 g_wl[(size_t)NCLUST*P_DIM*S_DIM];
__device__ int g_order[NPAD];

// ---- PTX helpers (all family-portable, sm_80/75 era) ----
__device__ __forceinline__ uint32_t smem_u32(const void* p) {
    uint32_t a;
    asm("{ .reg .u64 t; cvta.to.shared.u64 t, %1; cvt.u32.u64 %0, t; }" : "=r"(a) : "l"(p));
    return a;
}
#define CP16(dst,src) asm volatile("cp.async.cg.shared.global [%0], [%1], 16;" :: "r"(dst), "l"(src) : "memory")
#define CP_COMMIT()   asm volatile("cp.async.commit_group;" ::: "memory")
#define CP_WAIT(n)    asm volatile("cp.async.wait_group %0;" :: "n"(n) : "memory")
#define ZERO16(a)     asm volatile("st.shared.v4.b32 [%0], {%1,%1,%1,%1};" :: "r"(a), "r"(0) : "memory")

#define LDSM4(r, a) asm volatile("ldmatrix.sync.aligned.m8n8.x4.shared.b16 {%0,%1,%2,%3}, [%4];" \
    : "=r"((r)[0]),"=r"((r)[1]),"=r"((r)[2]),"=r"((r)[3]) : "r"(a))
#define LDSM2(r, a) asm volatile("ldmatrix.sync.aligned.m8n8.x2.shared.b16 {%0,%1}, [%2];" \
    : "=r"((r)[0]),"=r"((r)[1]) : "r"(a))
#define MMA(c, a, b) asm volatile( \
    "mma.sync.aligned.m16n8k16.row.col.f32.bf16.bf16.f32 " \
    "{%0,%1,%2,%3},{%4,%5,%6,%7},{%8,%9},{%0,%1,%2,%3};" \
    : "+f"((c)[0]),"+f"((c)[1]),"+f"((c)[2]),"+f"((c)[3]) \
    : "r"((a)[0]),"r"((a)[1]),"r"((a)[2]),"r"((a)[3]),"r"((b)[0]),"r"((b)[1]))

// ---- prep kernels ----
__global__ void convert_x(const float* __restrict__ src) {
    size_t i = (size_t)blockIdx.x * blockDim.x + threadIdx.x;
    const size_t n4 = (size_t)B_DIM * C_DIM * S_DIM / 4;
    if (i >= n4) return;
    float4 v = ((const float4*)src)[i];
    float vv[4] = {v.x, v.y, v.z, v.w};
    __nv_bfloat16 h[4], l[4];
    #pragma unroll
    for (int j = 0; j < 4; ++j) {
        h[j] = __float2bfloat16_rn(vv[j]);
        l[j] = __float2bfloat16_rn(vv[j] - __bfloat162float(h[j]));
    }
    ((uint2*)g_xh)[i] = *(uint2*)h;
    ((uint2*)g_xl)[i] = *(uint2*)l;
}
__global__ void convert_w(const float* __restrict__ src) {
    size_t i = (size_t)blockIdx.x * blockDim.x + threadIdx.x;
    const size_t n4 = (size_t)NCLUST * P_DIM * S_DIM / 4;
    if (i >= n4) return;
    float4 v = ((const float4*)src)[i];
    float vv[4] = {v.x, v.y, v.z, v.w};
    __nv_bfloat16 h[4], l[4];
    #pragma unroll
    for (int j = 0; j < 4; ++j) {
        h[j] = __float2bfloat16_rn(vv[j]);
        l[j] = __float2bfloat16_rn(vv[j] - __bfloat162float(h[j]));
    }
    ((uint2*)g_wh)[i] = *(uint2*)h;
    ((uint2*)g_wl)[i] = *(uint2*)l;
}

// stable cluster-sorted channel order, per-cluster padded to even with -1
__global__ void build_order(const int* __restrict__ clusters) {
    __shared__ int cl[C_DIM];
    __shared__ int cnt[NCLUST];
    int t = threadIdx.x;
    for (int i = t; i < C_DIM; i += blockDim.x) {
        int k = clusters[i];
        cl[i] = min(max(k, 0), NCLUST - 1);
    }
    for (int i = t; i < NPAD; i += blockDim.x) g_order[i] = -1;
    __syncthreads();
    if (t < NCLUST) {
        int c = 0;
        for (int i = 0; i < C_DIM; ++i) c += (cl[i] == t);
        cnt[t] = c;
    }
    __syncthreads();
    if (t < C_DIM) {
        int k = cl[t];
        int off = 0;
        for (int j = 0; j < NCLUST; ++j) if (j < k) off += (cnt[j] + 1) & ~1;
        int rank = 0;
        for (int i = 0; i < t; ++i) rank += (cl[i] == k);
        g_order[off + rank] = t;
    }
}

// ---- GEMM ----
__device__ __forceinline__ void load_stage(uint32_t st, int k0, bool tail,
                                           int ch0, int ch1, int kcl,
                                           int n_base, int tid) {
    // A: 128 rows (64 batch x ch0, 64 batch x ch1), 64B of K data per row
    #pragma unroll 2
    for (int v = tid; v < 512; v += 256) {
        int r = v >> 2, q = v & 3;
        int b = r & 63;
        int c = (r >> 6) ? ch1 : ch0;
        size_t so = ((size_t)b * C_DIM + c) * S_DIM + k0 + q * 8;
        uint32_t d = st + OFF_AH + r * ROWB + q * 16;
        if (!tail || q < 2) {
            CP16(d, g_xh + so);
            CP16(d + (OFF_AL - OFF_AH), g_xl + so);
        } else {
            ZERO16(d);
            ZERO16(d + (OFF_AL - OFF_AH));
        }
    }
    // B: 112 rows (output cols), 64B of K data per row
    #pragma unroll 2
    for (int v = tid; v < 448; v += 256) {
        int r = v >> 2, q = v & 3;
        size_t so = ((size_t)kcl * P_DIM + n_base + r) * S_DIM + k0 + q * 8;
        uint32_t d = st + OFF_BH + r * ROWB + q * 16;
        if (!tail || q < 2) {
            CP16(d, g_wh + so);
            CP16(d + (OFF_BL - OFF_BH), g_wl + so);
        } else {
            ZERO16(d);
            ZERO16(d + (OFF_BL - OFF_BH));
        }
    }
}

__global__ __launch_bounds__(256, 1)
void gemm_kernel(const int* __restrict__ clusters,
                 const float* __restrict__ bias,
                 float* __restrict__ out) {
    extern __shared__ char smem[];
    const uint32_t sbase = smem_u32(smem);
    const int tid  = threadIdx.x;
    const int lane = tid & 31;
    const int wid  = tid >> 5;
    const int warpM = wid & 3;      // 4 M-warps
    const int warpN = wid >> 2;     // 2 N-warps
    const int mrow0 = warpM * 32;
    const int nrow0 = warpN * 56;

    const int tile   = blockIdx.y;
    const int n_base = blockIdx.x * TILE_N;

    int ch0 = g_order[2 * tile];
    int ch1 = g_order[2 * tile + 1];
    if (ch0 < 0) return;               // fully-dummy tile (whole CTA exits)
    const bool valid1 = (ch1 >= 0);
    if (!valid1) ch1 = ch0;            // duplicate loads, skip stores
    int kcl = clusters[ch0];
    kcl = min(max(kcl, 0), NCLUST - 1);

    float acc[2][7][4] = {};

    // prologue: fill pipeline
    #pragma unroll
    for (int s = 0; s < NSTAGES; ++s) {
        load_stage(sbase + s * STAGE_B, s * KC, false, ch0, ch1, kcl, n_base, tid);
        CP_COMMIT();
    }

    for (int chunk = 0; chunk < NCHUNKS; ++chunk) {
        CP_WAIT(NSTAGES - 1);
        __syncthreads();

        const uint32_t st = sbase + (chunk & (NSTAGES - 1)) * STAGE_B;
        #pragma unroll
        for (int ks = 0; ks < 2; ++ks) {
            const int kb = ks * 32;
            uint32_t ah[2][4], al[2][4];
            #pragma unroll
            for (int mf = 0; mf < 2; ++mf) {
                uint32_t a = st + OFF_AH +
                    (uint32_t)(mrow0 + mf * 16 + (lane & 15)) * ROWB +
                    kb + ((lane >> 4) << 4);
                LDSM4(ah[mf], a);
                LDSM4(al[mf], a + (OFF_AL - OFF_AH));
            }
            uint32_t bh[7][2], bl[7][2];
            #pragma unroll
            for (int nf = 0; nf < 7; ++nf) {
                uint32_t a = st + OFF_BH +
                    (uint32_t)(nrow0 + nf * 8 + (lane & 7)) * ROWB +
                    kb + (((lane >> 3) & 1) << 4);
                LDSM2(bh[nf], a);
                LDSM2(bl[nf], a + (OFF_BL - OFF_BH));
            }
            #pragma unroll
            for (int mf = 0; mf < 2; ++mf)
                #pragma unroll
                for (int nf = 0; nf < 7; ++nf) {
                    MMA(acc[mf][nf], ah[mf], bh[nf]);
                    MMA(acc[mf][nf], ah[mf], bl[nf]);
                    MMA(acc[mf][nf], al[mf], bh[nf]);
                }
        }
        __syncthreads();

        const int nx = chunk + NSTAGES;
        if (nx < NCHUNKS)
            load_stage(sbase + (nx & (NSTAGES - 1)) * STAGE_B, nx * KC,
                       nx == NCHUNKS - 1, ch0, ch1, kcl, n_base, tid);
        CP_COMMIT();
    }

    // epilogue: bias + store
    const float* biasrow = bias + (size_t)kcl * P_DIM + n_base + nrow0;
    #pragma unroll
    for (int mf = 0; mf < 2; ++mf) {
        const int m0 = mrow0 + mf * 16 + (lane >> 2);   // rows m0, m0+8 (same half)
        const bool hi_half = (m0 >= 64);
        if (hi_half && !valid1) continue;
        const int b0 = hi_half ? m0 - 64 : m0;
        const int cc = hi_half ? ch1 : ch0;
        float* o0 = out + ((size_t)b0 * C_DIM + cc) * P_DIM + n_base + nrow0;
        float* o1 = o0 + (size_t)8 * C_DIM * P_DIM;     // row m0+8: batch b0+8
        #pragma unroll
        for (int nf = 0; nf < 7; ++nf) {
            const int col = nf * 8 + (lane & 3) * 2;
            float2 bb = *(const float2*)(biasrow + col);
            float2 v0, v1;
            v0.x = acc[mf][nf][0] + bb.x;
            v0.y = acc[mf][nf][1] + bb.y;
            v1.x = acc[mf][nf][2] + bb.x;
            v1.y = acc[mf][nf][3] + bb.y;
            *(float2*)(o0 + col) = v0;
            *(float2*)(o1 + col) = v1;
        }
    }
}

extern "C" void kernel_launch(void* const* d_in, const int* in_sizes, int n_in,
                              void* d_out, int out_size) {
    const float* x        = (const float*)d_in[0];
    const int*   clusters = (const int*)d_in[1];
    const float* W        = (const float*)d_in[2];
    const float* bias     = (const float*)d_in[3];
    float*       out      = (float*)d_out;

    cudaFuncSetAttribute(gemm_kernel, cudaFuncAttributeMaxDynamicSharedMemorySize, SMEM_TOTAL);

    convert_x<<<(int)(((size_t)B_DIM*C_DIM*S_DIM/4 + 255)/256), 256>>>(x);
    convert_w<<<(int)(((size_t)NCLUST*P_DIM*S_DIM/4 + 255)/256), 256>>>(W);
    build_order<<<1, 896>>>(clusters);
    gemm_kernel<<<dim3(3, NTILES), 256, SMEM_TOTAL>>>(clusters, bias, out);
}

// round 6
// speedup vs baseline: 2.2934x; 1.0116x over previous
#include <cuda_runtime.h>
#include <cuda_bf16.h>
#include <cstdint>

// ClusteredLinear via cluster-paired bf16-split mma.sync GEMM.
// out[b,c,p] = sum_s x[b,c,s]*W[cl[c],p,s] + bias[cl[c],p]
// R5: 512 threads / 16 warps (8M x 2N, warp tile m16n56), single-barrier
// 4-stage cp.async pipeline, LDSM x4-paired B fragment loads.

#define B_DIM 64
#define C_DIM 862
#define S_DIM 720
#define P_DIM 336
#define NCLUST 8

#define TILE_N 112
#define KC 32
#define NCHUNKS 23          // 22 full + 16-elem zero-padded tail
#define NSTAGES 4
#define NTILES 435
#define NPAD 880

#define ROWB 80                       // padded smem row stride (bytes)
#define OFF_AH 0
#define OFF_AL (128*ROWB)
#define OFF_BH (OFF_AL + 128*ROWB)
#define OFF_BL (OFF_BH + TILE_N*ROWB)
#define STAGE_B (OFF_BL + TILE_N*ROWB)   // 38400
#define SMEM_TOTAL (NSTAGES*STAGE_B)     // 153600

// ---- scratch ----
__device__ __nv_bfloat16 g_xh[(size_t)B_DIM*C_DIM*S_DIM];
__device__ __nv_bfloat16 g_xl[(size_t)B_DIM*C_DIM*S_DIM];
__device__ __nv_bfloat16 g_wh[(size_t)NCLUST*P_DIM*S_DIM];
__device__ __nv_bfloat16 g_wl[(size_t)NCLUST*P_DIM*S_DIM];
__device__ int g_order[NPAD];

// ---- PTX helpers (family-portable) ----
__device__ __forceinline__ uint32_t smem_u32(const void* p) {
    uint32_t a;
    asm("{ .reg .u64 t; cvta.to.shared.u64 t, %1; cvt.u32.u64 %0, t; }" : "=r"(a) : "l"(p));
    return a;
}
#define CP16(dst,src) asm volatile("cp.async.cg.shared.global [%0], [%1], 16;" :: "r"(dst), "l"(src) : "memory")
#define CP_COMMIT()   asm volatile("cp.async.commit_group;" ::: "memory")
#define CP_WAIT(n)    asm volatile("cp.async.wait_group %0;" :: "n"(n) : "memory")
#define ZERO16(a)     asm volatile("st.shared.v4.b32 [%0], {%1,%1,%1,%1};" :: "r"(a), "r"(0) : "memory")

#define LDSM4(r, a) asm volatile("ldmatrix.sync.aligned.m8n8.x4.shared.b16 {%0,%1,%2,%3}, [%4];" \
    : "=r"((r)[0]),"=r"((r)[1]),"=r"((r)[2]),"=r"((r)[3]) : "r"(a))
#define LDSM2(r, a) asm volatile("ldmatrix.sync.aligned.m8n8.x2.shared.b16 {%0,%1}, [%2];" \
    : "=r"((r)[0]),"=r"((r)[1]) : "r"(a))
#define MMA(c, a, b) asm volatile( \
    "mma.sync.aligned.m16n8k16.row.col.f32.bf16.bf16.f32 " \
    "{%0,%1,%2,%3},{%4,%5,%6,%7},{%8,%9},{%0,%1,%2,%3};" \
    : "+f"((c)[0]),"+f"((c)[1]),"+f"((c)[2]),"+f"((c)[3]) \
    : "r"((a)[0]),"r"((a)[1]),"r"((a)[2]),"r"((a)[3]),"r"((b)[0]),"r"((b)[1]))

// ---- prep kernels ----
__global__ void convert_x(const float* __restrict__ src) {
    size_t i = (size_t)blockIdx.x * blockDim.x + threadIdx.x;
    const size_t n4 = (size_t)B_DIM * C_DIM * S_DIM / 4;
    if (i >= n4) return;
    float4 v = ((const float4*)src)[i];
    float vv[4] = {v.x, v.y, v.z, v.w};
    __nv_bfloat16 h[4], l[4];
    #pragma unroll
    for (int j = 0; j < 4; ++j) {
        h[j] = __float2bfloat16_rn(vv[j]);
        l[j] = __float2bfloat16_rn(vv[j] - __bfloat162float(h[j]));
    }
    ((uint2*)g_xh)[i] = *(uint2*)h;
    ((uint2*)g_xl)[i] = *(uint2*)l;
}
__global__ void convert_w(const float* __restrict__ src) {
    size_t i = (size_t)blockIdx.x * blockDim.x + threadIdx.x;
    const size_t n4 = (size_t)NCLUST * P_DIM * S_DIM / 4;
    if (i >= n4) return;
    float4 v = ((const float4*)src)[i];
    float vv[4] = {v.x, v.y, v.z, v.w};
    __nv_bfloat16 h[4], l[4];
    #pragma unroll
    for (int j = 0; j < 4; ++j) {
        h[j] = __float2bfloat16_rn(vv[j]);
        l[j] = __float2bfloat16_rn(vv[j] - __bfloat162float(h[j]));
    }
    ((uint2*)g_wh)[i] = *(uint2*)h;
    ((uint2*)g_wl)[i] = *(uint2*)l;
}

__global__ void build_order(const int* __restrict__ clusters) {
    __shared__ int cl[C_DIM];
    __shared__ int cnt[NCLUST];
    int t = threadIdx.x;
    for (int i = t; i < C_DIM; i += blockDim.x) {
        int k = clusters[i];
        cl[i] = min(max(k, 0), NCLUST - 1);
    }
    for (int i = t; i < NPAD; i += blockDim.x) g_order[i] = -1;
    __syncthreads();
    if (t < NCLUST) {
        int c = 0;
        for (int i = 0; i < C_DIM; ++i) c += (cl[i] == t);
        cnt[t] = c;
    }
    __syncthreads();
    if (t < C_DIM) {
        int k = cl[t];
        int off = 0;
        for (int j = 0; j < NCLUST; ++j) if (j < k) off += (cnt[j] + 1) & ~1;
        int rank = 0;
        for (int i = 0; i < t; ++i) rank += (cl[i] == k);
        g_order[off + rank] = t;
    }
}

// ---- GEMM ----
__device__ __forceinline__ void load_stage(uint32_t st, int k0, bool tail,
                                           int ch0, int ch1, int kcl,
                                           int n_base, int tid) {
    // A: 128 rows x 64B of K, hi+lo. 512 threads -> one 16B vec each.
    {
        int r = tid >> 2, q = tid & 3;
        int b = r & 63;
        int c = (r >> 6) ? ch1 : ch0;
        size_t so = ((size_t)b * C_DIM + c) * S_DIM + k0 + q * 8;
        uint32_t d = st + OFF_AH + r * ROWB + q * 16;
        if (!tail || q < 2) {
            CP16(d, g_xh + so);
            CP16(d + (OFF_AL - OFF_AH), g_xl + so);
        } else {
            ZERO16(d);
            ZERO16(d + (OFF_AL - OFF_AH));
        }
    }
    // B: 112 rows x 64B of K, hi+lo. threads 0..447.
    if (tid < 448) {
        int r = tid >> 2, q = tid & 3;
        size_t so = ((size_t)kcl * P_DIM + n_base + r) * S_DIM + k0 + q * 8;
        uint32_t d = st + OFF_BH + r * ROWB + q * 16;
        if (!tail || q < 2) {
            CP16(d, g_wh + so);
            CP16(d + (OFF_BL - OFF_BH), g_wl + so);
        } else {
            ZERO16(d);
            ZERO16(d + (OFF_BL - OFF_BH));
        }
    }
}

__global__ __launch_bounds__(512, 1)
void gemm_kernel(const int* __restrict__ clusters,
                 const float* __restrict__ bias,
                 float* __restrict__ out) {
    extern __shared__ char smem[];
    const uint32_t sbase = smem_u32(smem);
    const int tid  = threadIdx.x;
    const int lane = tid & 31;
    const int wid  = tid >> 5;
    const int warpM = wid & 7;      // 8 M-warps (m16 each)
    const int warpN = wid >> 3;     // 2 N-warps (n56 each)
    const int mrow0 = warpM * 16;
    const int nrow0 = warpN * 56;

    const int tile   = blockIdx.y;
    const int n_base = blockIdx.x * TILE_N;

    int ch0 = g_order[2 * tile];
    int ch1 = g_order[2 * tile + 1];
    if (ch0 < 0) return;
    const bool valid1 = (ch1 >= 0);
    if (!valid1) ch1 = ch0;
    int kcl = clusters[ch0];
    kcl = min(max(kcl, 0), NCLUST - 1);

    float acc[7][4] = {};

    // Precompute ldmatrix smem addresses (stage-0 based, add stage offset later).
    // A (m16k16, .row): lanes 0-7 -> m0-7 k0; 8-15 -> m8-15 k0; 16-23 -> m0-7 k8;
    // 24-31 -> m8-15 k8.  (same mapping as proven R4 code)
    const uint32_t a_addr0 = sbase + OFF_AH +
        (uint32_t)(mrow0 + (lane & 15)) * ROWB + ((lane >> 4) << 4);
    // B paired x4 (two n8 fragments): group g=lane>>3: rows (pair*16 + (g>=2)*8
    // + (lane&7)), col +16B for odd g.
    const uint32_t b_addr_pair0 = sbase + OFF_BH +
        (uint32_t)(nrow0 + ((lane >> 4) << 3) + (lane & 7)) * ROWB +
        (((lane >> 3) & 1) << 4);
    // B last fragment (nf=6) x2: lanes 0-7 rows, 8-15 +16B (lanes>=16 replicate)
    const uint32_t b_addr_last0 = sbase + OFF_BH +
        (uint32_t)(nrow0 + 48 + (lane & 7)) * ROWB + (((lane >> 3) & 1) << 4);

    // prologue: stages 0..NSTAGES-2
    #pragma unroll
    for (int s = 0; s < NSTAGES - 1; ++s) {
        load_stage(sbase + s * STAGE_B, s * KC, false, ch0, ch1, kcl, n_base, tid);
        CP_COMMIT();
    }

    for (int chunk = 0; chunk < NCHUNKS; ++chunk) {
        CP_WAIT(NSTAGES - 2);
        __syncthreads();

        // issue loads for chunk+NSTAGES-1 into the slot freed last iteration
        const int nx = chunk + NSTAGES - 1;
        if (nx < NCHUNKS)
            load_stage(sbase + (nx & (NSTAGES - 1)) * STAGE_B, nx * KC,
                       nx == NCHUNKS - 1, ch0, ch1, kcl, n_base, tid);
        CP_COMMIT();   // commit (possibly empty) to keep group accounting fixed

        const uint32_t so = (uint32_t)(chunk & (NSTAGES - 1)) * STAGE_B;
        #pragma unroll
        for (int ks = 0; ks < 2; ++ks) {
            const int kb = ks * 32;
            uint32_t ah[4], al[4];
            LDSM4(ah, a_addr0 + so + kb);
            LDSM4(al, a_addr0 + so + kb + (OFF_AL - OFF_AH));

            uint32_t bh[7][2], bl[7][2];
            #pragma unroll
            for (int p = 0; p < 3; ++p) {
                uint32_t a = b_addr_pair0 + so + kb + (uint32_t)p * 16 * ROWB;
                uint32_t r4[4];
                LDSM4(r4, a);
                bh[2*p][0] = r4[0]; bh[2*p][1] = r4[1];
                bh[2*p+1][0] = r4[2]; bh[2*p+1][1] = r4[3];
                LDSM4(r4, a + (OFF_BL - OFF_BH));
                bl[2*p][0] = r4[0]; bl[2*p][1] = r4[1];
                bl[2*p+1][0] = r4[2]; bl[2*p+1][1] = r4[3];
            }
            LDSM2(bh[6], b_addr_last0 + so + kb);
            LDSM2(bl[6], b_addr_last0 + so + kb + (OFF_BL - OFF_BH));

            #pragma unroll
            for (int nf = 0; nf < 7; ++nf) {
                MMA(acc[nf], ah, bh[nf]);
                MMA(acc[nf], ah, bl[nf]);
                MMA(acc[nf], al, bh[nf]);
            }
        }
    }

    // epilogue: bias + store (warp rows mrow0 + lane>>2, +8; all in one half)
    const float* biasrow = bias + (size_t)kcl * P_DIM + n_base + nrow0;
    const int m0 = mrow0 + (lane >> 2);
    const bool hi_half = (m0 >= 64);
    if (!hi_half || valid1) {
        const int b0 = hi_half ? m0 - 64 : m0;
        const int cc = hi_half ? ch1 : ch0;
        float* o0 = out + ((size_t)b0 * C_DIM + cc) * P_DIM + n_base + nrow0;
        float* o1 = o0 + (size_t)8 * C_DIM * P_DIM;
        #pragma unroll
        for (int nf = 0; nf < 7; ++nf) {
            const int col = nf * 8 + (lane & 3) * 2;
            float2 bb = *(const float2*)(biasrow + col);
            float2 v0, v1;
            v0.x = acc[nf][0] + bb.x;
            v0.y = acc[nf][1] + bb.y;
            v1.x = acc[nf][2] + bb.x;
            v1.y = acc[nf][3] + bb.y;
            *(float2*)(o0 + col) = v0;
            *(float2*)(o1 + col) = v1;
        }
    }
}

extern "C" void kernel_launch(void* const* d_in, const int* in_sizes, int n_in,
                              void* d_out, int out_size) {
    const float* x        = (const float*)d_in[0];
    const int*   clusters = (const int*)d_in[1];
    const float* W        = (const float*)d_in[2];
    const float* bias     = (const float*)d_in[3];
    float*       out      = (float*)d_out;

    cudaFuncSetAttribute(gemm_kernel, cudaFuncAttributeMaxDynamicSharedMemorySize, SMEM_TOTAL);

    convert_x<<<(int)(((size_t)B_DIM*C_DIM*S_DIM/4 + 255)/256), 256>>>(x);
    convert_w<<<(int)(((size_t)NCLUST*P_DIM*S_DIM/4 + 255)/256), 256>>>(W);
    build_order<<<1, 896>>>(clusters);
    gemm_kernel<<<dim3(3, NTILES), 512, SMEM_TOTAL>>>(clusters, bias, out);
}

// round 7
// speedup vs baseline: 2.9663x; 1.2934x over previous
#include <cuda_runtime.h>
#include <cuda_fp16.h>
#include <cstdint>

// ClusteredLinear via cluster-paired fp16-split mma.sync GEMM.
// out[b,c,p] = sum_s x[b,c,s]*W[cl[c],p,s] + bias[cl[c],p]
// R6: 2-pass fp16 split: (xh + xl) * wh = x * wh exactly; dropped term
// x*(w-wh) is ~2^-11 relative (~1e-4..6e-4) — under the 1e-3 gate.
// 512 threads / 16 warps (8M x 2N, warp tile m16n56), single-barrier
// 4-stage cp.async pipeline, LDSM x4-paired B fragment loads.

#define B_DIM 64
#define C_DIM 862
#define S_DIM 720
#define P_DIM 336
#define NCLUST 8

#define TILE_N 112
#define KC 32
#define NCHUNKS 23          // 22 full + 16-elem zero-padded tail
#define NSTAGES 4
#define NTILES 435
#define NPAD 880

#define ROWB 80                       // padded smem row stride (bytes)
#define OFF_AH 0
#define OFF_AL (128*ROWB)             // 10240
#define OFF_BH (OFF_AL + 128*ROWB)    // 20480
#define STAGE_B (OFF_BH + TILE_N*ROWB)   // 29440
#define SMEM_TOTAL (NSTAGES*STAGE_B)     // 117760

// ---- scratch ----
__device__ __half g_xh[(size_t)B_DIM*C_DIM*S_DIM];
__device__ __half g_xl[(size_t)B_DIM*C_DIM*S_DIM];
__device__ __half g_wh[(size_t)NCLUST*P_DIM*S_DIM];
__device__ int g_order[NPAD];

// ---- PTX helpers (family-portable) ----
__device__ __forceinline__ uint32_t smem_u32(const void* p) {
    uint32_t a;
    asm("{ .reg .u64 t; cvta.to.shared.u64 t, %1; cvt.u32.u64 %0, t; }" : "=r"(a) : "l"(p));
    return a;
}
#define CP16(dst,src) asm volatile("cp.async.cg.shared.global [%0], [%1], 16;" :: "r"(dst), "l"(src) : "memory")
#define CP_COMMIT()   asm volatile("cp.async.commit_group;" ::: "memory")
#define CP_WAIT(n)    asm volatile("cp.async.wait_group %0;" :: "n"(n) : "memory")
#define ZERO16(a)     asm volatile("st.shared.v4.b32 [%0], {%1,%1,%1,%1};" :: "r"(a), "r"(0) : "memory")

#define LDSM4(r, a) asm volatile("ldmatrix.sync.aligned.m8n8.x4.shared.b16 {%0,%1,%2,%3}, [%4];" \
    : "=r"((r)[0]),"=r"((r)[1]),"=r"((r)[2]),"=r"((r)[3]) : "r"(a))
#define LDSM2(r, a) asm volatile("ldmatrix.sync.aligned.m8n8.x2.shared.b16 {%0,%1}, [%2];" \
    : "=r"((r)[0]),"=r"((r)[1]) : "r"(a))
#define MMA(c, a, b) asm volatile( \
    "mma.sync.aligned.m16n8k16.row.col.f32.f16.f16.f32 " \
    "{%0,%1,%2,%3},{%4,%5,%6,%7},{%8,%9},{%0,%1,%2,%3};" \
    : "+f"((c)[0]),"+f"((c)[1]),"+f"((c)[2]),"+f"((c)[3]) \
    : "r"((a)[0]),"r"((a)[1]),"r"((a)[2]),"r"((a)[3]),"r"((b)[0]),"r"((b)[1]))

// ---- prep kernels ----
__global__ void convert_x(const float* __restrict__ src) {
    size_t i = (size_t)blockIdx.x * blockDim.x + threadIdx.x;
    const size_t n4 = (size_t)B_DIM * C_DIM * S_DIM / 4;
    if (i >= n4) return;
    float4 v = ((const float4*)src)[i];
    float vv[4] = {v.x, v.y, v.z, v.w};
    __half h[4], l[4];
    #pragma unroll
    for (int j = 0; j < 4; ++j) {
        h[j] = __float2half_rn(vv[j]);
        l[j] = __float2half_rn(vv[j] - __half2float(h[j]));
    }
    ((uint2*)g_xh)[i] = *(uint2*)h;
    ((uint2*)g_xl)[i] = *(uint2*)l;
}
__global__ void convert_w(const float* __restrict__ src) {
    size_t i = (size_t)blockIdx.x * blockDim.x + threadIdx.x;
    const size_t n4 = (size_t)NCLUST * P_DIM * S_DIM / 4;
    if (i >= n4) return;
    float4 v = ((const float4*)src)[i];
    float vv[4] = {v.x, v.y, v.z, v.w};
    __half h[4];
    #pragma unroll
    for (int j = 0; j < 4; ++j) h[j] = __float2half_rn(vv[j]);
    ((uint2*)g_wh)[i] = *(uint2*)h;
}

__global__ void build_order(const int* __restrict__ clusters) {
    __shared__ int cl[C_DIM];
    __shared__ int cnt[NCLUST];
    int t = threadIdx.x;
    for (int i = t; i < C_DIM; i += blockDim.x) {
        int k = clusters[i];
        cl[i] = min(max(k, 0), NCLUST - 1);
    }
    for (int i = t; i < NPAD; i += blockDim.x) g_order[i] = -1;
    __syncthreads();
    if (t < NCLUST) {
        int c = 0;
        for (int i = 0; i < C_DIM; ++i) c += (cl[i] == t);
        cnt[t] = c;
    }
    __syncthreads();
    if (t < C_DIM) {
        int k = cl[t];
        int off = 0;
        for (int j = 0; j < NCLUST; ++j) if (j < k) off += (cnt[j] + 1) & ~1;
        int rank = 0;
        for (int i = 0; i < t; ++i) rank += (cl[i] == k);
        g_order[off + rank] = t;
    }
}

// ---- GEMM ----
__device__ __forceinline__ void load_stage(uint32_t st, int k0, bool tail,
                                           int ch0, int ch1, int kcl,
                                           int n_base, int tid) {
    // A: 128 rows x 64B of K, hi+lo. 512 threads -> one 16B vec each.
    {
        int r = tid >> 2, q = tid & 3;
        int b = r & 63;
        int c = (r >> 6) ? ch1 : ch0;
        size_t so = ((size_t)b * C_DIM + c) * S_DIM + k0 + q * 8;
        uint32_t d = st + OFF_AH + r * ROWB + q * 16;
        if (!tail || q < 2) {
            CP16(d, g_xh + so);
            CP16(d + (OFF_AL - OFF_AH), g_xl + so);
        } else {
            ZERO16(d);
            ZERO16(d + (OFF_AL - OFF_AH));
        }
    }
    // B: 112 rows x 64B of K, hi only. threads 0..447.
    if (tid < 448) {
        int r = tid >> 2, q = tid & 3;
        size_t so = ((size_t)kcl * P_DIM + n_base + r) * S_DIM + k0 + q * 8;
        uint32_t d = st + OFF_BH + r * ROWB + q * 16;
        if (!tail || q < 2) {
            CP16(d, g_wh + so);
        } else {
            ZERO16(d);
        }
    }
}

__global__ __launch_bounds__(512, 1)
void gemm_kernel(const int* __restrict__ clusters,
                 const float* __restrict__ bias,
                 float* __restrict__ out) {
    extern __shared__ char smem[];
    const uint32_t sbase = smem_u32(smem);
    const int tid  = threadIdx.x;
    const int lane = tid & 31;
    const int wid  = tid >> 5;
    const int warpM = wid & 7;      // 8 M-warps (m16 each)
    const int warpN = wid >> 3;     // 2 N-warps (n56 each)
    const int mrow0 = warpM * 16;
    const int nrow0 = warpN * 56;

    const int tile   = blockIdx.y;
    const int n_base = blockIdx.x * TILE_N;

    int ch0 = g_order[2 * tile];
    int ch1 = g_order[2 * tile + 1];
    if (ch0 < 0) return;
    const bool valid1 = (ch1 >= 0);
    if (!valid1) ch1 = ch0;
    int kcl = clusters[ch0];
    kcl = min(max(kcl, 0), NCLUST - 1);

    float acc[7][4] = {};

    // ldmatrix base addresses (stage 0; add stage offset per chunk).
    const uint32_t a_addr0 = sbase + OFF_AH +
        (uint32_t)(mrow0 + (lane & 15)) * ROWB + ((lane >> 4) << 4);
    const uint32_t b_addr_pair0 = sbase + OFF_BH +
        (uint32_t)(nrow0 + ((lane >> 4) << 3) + (lane & 7)) * ROWB +
        (((lane >> 3) & 1) << 4);
    const uint32_t b_addr_last0 = sbase + OFF_BH +
        (uint32_t)(nrow0 + 48 + (lane & 7)) * ROWB + (((lane >> 3) & 1) << 4);

    // prologue: stages 0..NSTAGES-2
    #pragma unroll
    for (int s = 0; s < NSTAGES - 1; ++s) {
        load_stage(sbase + s * STAGE_B, s * KC, false, ch0, ch1, kcl, n_base, tid);
        CP_COMMIT();
    }

    for (int chunk = 0; chunk < NCHUNKS; ++chunk) {
        CP_WAIT(NSTAGES - 2);
        __syncthreads();

        const int nx = chunk + NSTAGES - 1;
        if (nx < NCHUNKS)
            load_stage(sbase + (nx & (NSTAGES - 1)) * STAGE_B, nx * KC,
                       nx == NCHUNKS - 1, ch0, ch1, kcl, n_base, tid);
        CP_COMMIT();

        const uint32_t so = (uint32_t)(chunk & (NSTAGES - 1)) * STAGE_B;
        #pragma unroll
        for (int ks = 0; ks < 2; ++ks) {
            const int kb = ks * 32;
            uint32_t ah[4], al[4];
            LDSM4(ah, a_addr0 + so + kb);
            LDSM4(al, a_addr0 + so + kb + (OFF_AL - OFF_AH));

            uint32_t bh[7][2];
            #pragma unroll
            for (int p = 0; p < 3; ++p) {
                uint32_t a = b_addr_pair0 + so + kb + (uint32_t)p * 16 * ROWB;
                uint32_t r4[4];
                LDSM4(r4, a);
                bh[2*p][0] = r4[0]; bh[2*p][1] = r4[1];
                bh[2*p+1][0] = r4[2]; bh[2*p+1][1] = r4[3];
            }
            LDSM2(bh[6], b_addr_last0 + so + kb);

            #pragma unroll
            for (int nf = 0; nf < 7; ++nf) {
                MMA(acc[nf], ah, bh[nf]);
                MMA(acc[nf], al, bh[nf]);
            }
        }
    }

    // epilogue: bias + store
    const float* biasrow = bias + (size_t)kcl * P_DIM + n_base + nrow0;
    const int m0 = mrow0 + (lane >> 2);
    const bool hi_half = (m0 >= 64);
    if (!hi_half || valid1) {
        const int b0 = hi_half ? m0 - 64 : m0;
        const int cc = hi_half ? ch1 : ch0;
        float* o0 = out + ((size_t)b0 * C_DIM + cc) * P_DIM + n_base + nrow0;
        float* o1 = o0 + (size_t)8 * C_DIM * P_DIM;
        #pragma unroll
        for (int nf = 0; nf < 7; ++nf) {
            const int col = nf * 8 + (lane & 3) * 2;
            float2 bb = *(const float2*)(biasrow + col);
            float2 v0, v1;
            v0.x = acc[nf][0] + bb.x;
            v0.y = acc[nf][1] + bb.y;
            v1.x = acc[nf][2] + bb.x;
            v1.y = acc[nf][3] + bb.y;
            *(float2*)(o0 + col) = v0;
            *(float2*)(o1 + col) = v1;
        }
    }
}

extern "C" void kernel_launch(void* const* d_in, const int* in_sizes, int n_in,
                              void* d_out, int out_size) {
    const float* x        = (const float*)d_in[0];
    const int*   clusters = (const int*)d_in[1];
    const float* W        = (const float*)d_in[2];
    const float* bias     = (const float*)d_in[3];
    float*       out      = (float*)d_out;

    cudaFuncSetAttribute(gemm_kernel, cudaFuncAttributeMaxDynamicSharedMemorySize, SMEM_TOTAL);

    convert_x<<<(int)(((size_t)B_DIM*C_DIM*S_DIM/4 + 255)/256), 256>>>(x);
    convert_w<<<(int)(((size_t)NCLUST*P_DIM*S_DIM/4 + 255)/256), 256>>>(W);
    build_order<<<1, 896>>>(clusters);
    gemm_kernel<<<dim3(3, NTILES), 512, SMEM_TOTAL>>>(clusters, bias, out);
}